// round 6
// baseline (speedup 1.0000x reference)
#include <cuda_runtime.h>
#include <cuda_fp16.h>
#include <cstdint>

#define BHN 16
#define SEQ 4096
#define HD 64
#define BM 128
#define BN 64
#define NTHREADS 128
#define KPITCH 72   // smem row pitch in halves (144B rows -> conflict-free LDSM)
#define NT (SEQ / BN)

// fp16 scratch copies of K and V (converted once per launch)
__device__ __half2 Ksc[BHN * SEQ * HD / 2];
__device__ __half2 Vsc[BHN * SEQ * HD / 2];

__device__ __forceinline__ float ex2f(float x) {
    float y;
    asm("ex2.approx.f32 %0, %1;" : "=f"(y) : "f"(x));
    return y;
}

__device__ __forceinline__ uint32_t packh2(float a, float b) {
    __half2 t = __floats2half2_rn(a, b);
    return reinterpret_cast<uint32_t&>(t);
}

__device__ __forceinline__ void mma16816(float c[4], const uint32_t a[4],
                                         uint32_t b0, uint32_t b1) {
    asm volatile(
        "mma.sync.aligned.m16n8k16.row.col.f32.f16.f16.f32 "
        "{%0,%1,%2,%3},{%4,%5,%6,%7},{%8,%9},{%0,%1,%2,%3};"
        : "+f"(c[0]), "+f"(c[1]), "+f"(c[2]), "+f"(c[3])
        : "r"(a[0]), "r"(a[1]), "r"(a[2]), "r"(a[3]), "r"(b0), "r"(b1));
}

__device__ __forceinline__ void ldsm_x4(uint32_t& r0, uint32_t& r1, uint32_t& r2,
                                        uint32_t& r3, uint32_t addr) {
    asm volatile("ldmatrix.sync.aligned.m8n8.x4.shared.b16 {%0,%1,%2,%3},[%4];"
                 : "=r"(r0), "=r"(r1), "=r"(r2), "=r"(r3) : "r"(addr));
}

__device__ __forceinline__ void ldsm_x4_t(uint32_t& r0, uint32_t& r1, uint32_t& r2,
                                          uint32_t& r3, uint32_t addr) {
    asm volatile("ldmatrix.sync.aligned.m8n8.x4.trans.shared.b16 {%0,%1,%2,%3},[%4];"
                 : "=r"(r0), "=r"(r1), "=r"(r2), "=r"(r3) : "r"(addr));
}

__device__ __forceinline__ void cpasync16(uint32_t dst, const void* src) {
    asm volatile("cp.async.cg.shared.global [%0],[%1],16;" :: "r"(dst), "l"(src));
}
__device__ __forceinline__ void cp_commit() {
    asm volatile("cp.async.commit_group;");
}
template <int N>
__device__ __forceinline__ void cp_wait() {
    asm volatile("cp.async.wait_group %0;" :: "n"(N));
}

// prefetch one [BN x HD] fp16 tile into padded smem, rows PERMUTED within each
// 16-key group: storage row s holds actual key a = ((s&6)<<1)|((s&8)>>2)|(s&1).
// This makes each MMA thread's owned S-columns actual-contiguous (float4 stores).
__device__ __forceinline__ void prefetch_tile(uint32_t dstbase, const __half* src,
                                              int tid) {
#pragma unroll
    for (int t = 0; t < 4; ++t) {
        int i = tid + t * NTHREADS;
        int r = i >> 3;
        int c8 = (i & 7) << 3;
        int s = r & 15;
        int a = ((s & 6) << 1) | ((s & 8) >> 2) | (s & 1);
        int srcr = (r & 48) | a;
        cpasync16(dstbase + (uint32_t)((r * KPITCH + c8) * 2), src + srcr * HD + c8);
    }
}

// ---------------- pre-conversion kernel ----------------
__global__ void __launch_bounds__(256)
convert_kernel(const float* __restrict__ K, const float* __restrict__ V) {
    const int n4 = BHN * SEQ * HD / 4;
    int i = blockIdx.x * blockDim.x + threadIdx.x;
    if (i < n4) {
        float4 f = reinterpret_cast<const float4*>(K)[i];
        Ksc[2 * i] = __floats2half2_rn(f.x, f.y);
        Ksc[2 * i + 1] = __floats2half2_rn(f.z, f.w);
    } else {
        int j = i - n4;
        float4 f = reinterpret_cast<const float4*>(V)[j];
        Vsc[2 * j] = __floats2half2_rn(f.x, f.y);
        Vsc[2 * j + 1] = __floats2half2_rn(f.z, f.w);
    }
}

// ---------------- main attention kernel ----------------
__global__ void __launch_bounds__(NTHREADS, 2)
attn_kernel(const float* __restrict__ Qg, float* __restrict__ out) {
    __shared__ __half Kb[3][BN * KPITCH];   // 3-stage, prefetch distance 2
    __shared__ __half Vb[2][BN * KPITCH];   // 2-stage, prefetch distance 1

    const int bh = blockIdx.y;
    const float* Qb = Qg + (size_t)bh * SEQ * HD;
    const __half* Kb16 = reinterpret_cast<const __half*>(Ksc) + (size_t)bh * SEQ * HD;
    const __half* Vb16 = reinterpret_cast<const __half*>(Vsc) + (size_t)bh * SEQ * HD;
    float* Ob = out + (size_t)bh * SEQ * HD;
    float* Ab = out + (size_t)BHN * SEQ * HD + (size_t)bh * SEQ * SEQ;

    const int tid = threadIdx.x;
    const int warp = tid >> 5;
    const int lane = tid & 31;
    const int g = lane >> 2;
    const int qq = lane & 3;
    const int row0 = blockIdx.x * BM + warp * 32;   // 32 rows per warp

    uint32_t bK[3], bV[2];
#pragma unroll
    for (int i = 0; i < 3; ++i)
        bK[i] = (uint32_t)__cvta_generic_to_shared(&Kb[i][0]);
#pragma unroll
    for (int i = 0; i < 2; ++i)
        bV[i] = (uint32_t)__cvta_generic_to_shared(&Vb[i][0]);

    // LDSM lane offsets
    const int qk_r = (lane & 7) + ((lane & 16) ? 8 : 0);
    const int qk_c = (lane & 8) ? 8 : 0;
    const uint32_t offK = (uint32_t)((qk_r * KPITCH + qk_c) * 2);
    const int v_r = (lane & 7) + ((lane & 8) ? 8 : 0);
    const int v_c = (lane & 16) ? 8 : 0;
    const uint32_t offV = (uint32_t)((v_r * KPITCH + v_c) * 2);
    const uint32_t NPOFF = 16 * KPITCH * 2;

    // ---- Q fragments fp16, two 16-row fragments per warp ----
    uint32_t qh[2][4][4];
#pragma unroll
    for (int rf = 0; rf < 2; ++rf)
#pragma unroll
        for (int kc = 0; kc < 4; ++kc)
#pragma unroll
            for (int p = 0; p < 4; ++p) {
                int r = row0 + rf * 16 + g + (p & 1) * 8;
                int d = kc * 16 + (p >> 1) * 8 + qq * 2;
                float2 f = *reinterpret_cast<const float2*>(Qb + (size_t)r * HD + d);
                qh[rf][kc][p] = packh2(f.x, f.y);
            }

    const float SC = 0.1803368801111244f;  // (1/sqrt(64)) * log2(e)

    // ================= PASS A: row sums =================
    float rs[2][2] = {};
    prefetch_tile(bK[0], Kb16, tid);
    cp_commit();
    prefetch_tile(bK[1], Kb16 + (size_t)BN * HD, tid);
    cp_commit();
    for (int kt = 0; kt < NT; ++kt) {
        if (kt + 1 < NT) cp_wait<1>(); else cp_wait<0>();
        __syncthreads();
        if (kt + 2 < NT) {
            prefetch_tile(bK[(kt + 2) % 3], Kb16 + (size_t)(kt + 2) * BN * HD, tid);
            cp_commit();
        }
        const uint32_t aK = bK[kt % 3] + offK;
        float c[2][8][4] = {};
#pragma unroll
        for (int kc = 0; kc < 4; ++kc) {
#pragma unroll
            for (int np = 0; np < 4; ++np) {
                uint32_t h0, h1, h2, h3;
                ldsm_x4(h0, h1, h2, h3, aK + np * NPOFF + kc * 32);
#pragma unroll
                for (int rf = 0; rf < 2; ++rf) {
                    mma16816(c[rf][2 * np], qh[rf][kc], h0, h1);
                    mma16816(c[rf][2 * np + 1], qh[rf][kc], h2, h3);
                }
            }
        }
#pragma unroll
        for (int rf = 0; rf < 2; ++rf)
#pragma unroll
            for (int nt = 0; nt < 8; ++nt) {
                rs[rf][0] += ex2f(c[rf][nt][0] * SC) + ex2f(c[rf][nt][1] * SC);
                rs[rf][1] += ex2f(c[rf][nt][2] * SC) + ex2f(c[rf][nt][3] * SC);
            }
    }
    float inv[2][2];
#pragma unroll
    for (int rf = 0; rf < 2; ++rf)
#pragma unroll
        for (int h = 0; h < 2; ++h) {
            float v = rs[rf][h];
            v += __shfl_xor_sync(0xffffffffu, v, 1);
            v += __shfl_xor_sync(0xffffffffu, v, 2);
            inv[rf][h] = 1.f / v;
        }

    // ========== PASS B: S, write attention, accumulate O ==========
    float o[2][8][4] = {};
    __syncthreads();   // pass-A tail: all warps done with K buffers
    prefetch_tile(bV[0], Vb16, tid);
    prefetch_tile(bK[0], Kb16, tid);
    cp_commit();
    prefetch_tile(bK[1], Kb16 + (size_t)BN * HD, tid);
    cp_commit();
    for (int kt = 0; kt < NT; ++kt) {
        if (kt + 1 < NT) cp_wait<1>(); else cp_wait<0>();
        __syncthreads();
        if (kt + 1 < NT) {
            prefetch_tile(bV[(kt + 1) & 1], Vb16 + (size_t)(kt + 1) * BN * HD, tid);
            cp_commit();
        }
        if (kt + 2 < NT) {
            prefetch_tile(bK[(kt + 2) % 3], Kb16 + (size_t)(kt + 2) * BN * HD, tid);
            cp_commit();
        }
        const uint32_t aK = bK[kt % 3] + offK;
        const uint32_t aV = bV[kt & 1] + offV;

        float c[2][8][4] = {};
#pragma unroll
        for (int kc = 0; kc < 4; ++kc) {
#pragma unroll
            for (int np = 0; np < 4; ++np) {
                uint32_t h0, h1, h2, h3;
                ldsm_x4(h0, h1, h2, h3, aK + np * NPOFF + kc * 32);
#pragma unroll
                for (int rf = 0; rf < 2; ++rf) {
                    mma16816(c[rf][2 * np], qh[rf][kc], h0, h1);
                    mma16816(c[rf][2 * np + 1], qh[rf][kc], h2, h3);
                }
            }
        }

        // exp + normalize + store attention as contiguous float4 (keys permuted)
#pragma unroll
        for (int rf = 0; rf < 2; ++rf) {
            const float i0 = inv[rf][0], i1 = inv[rf][1];
            float* arow0 = Ab + (size_t)(row0 + rf * 16 + g) * SEQ + kt * BN + qq * 4;
            float* arow1 = arow0 + 8 * SEQ;
#pragma unroll
            for (int P = 0; P < 4; ++P) {
                float* p0 = c[rf][2 * P];
                float* p1 = c[rf][2 * P + 1];
                p0[0] = ex2f(p0[0] * SC) * i0;
                p0[1] = ex2f(p0[1] * SC) * i0;
                p0[2] = ex2f(p0[2] * SC) * i1;
                p0[3] = ex2f(p0[3] * SC) * i1;
                p1[0] = ex2f(p1[0] * SC) * i0;
                p1[1] = ex2f(p1[1] * SC) * i0;
                p1[2] = ex2f(p1[2] * SC) * i1;
                p1[3] = ex2f(p1[3] * SC) * i1;
                // thread's actual columns: kt*64 + 16P + 4qq .. +3
                __stcs(reinterpret_cast<float4*>(arow0 + 16 * P),
                       make_float4(p0[0], p0[1], p1[0], p1[1]));
                __stcs(reinterpret_cast<float4*>(arow1 + 16 * P),
                       make_float4(p0[2], p0[3], p1[2], p1[3]));
            }
        }

        // AV: P (fp16, storage order) x V (fp16, rows in same storage order)
#pragma unroll
        for (int kcp = 0; kcp < 4; ++kcp) {
            const int t0 = 2 * kcp, t1 = 2 * kcp + 1;
            uint32_t ah[2][4];
#pragma unroll
            for (int rf = 0; rf < 2; ++rf) {
                ah[rf][0] = packh2(c[rf][t0][0], c[rf][t0][1]);
                ah[rf][1] = packh2(c[rf][t0][2], c[rf][t0][3]);
                ah[rf][2] = packh2(c[rf][t1][0], c[rf][t1][1]);
                ah[rf][3] = packh2(c[rf][t1][2], c[rf][t1][3]);
            }
#pragma unroll
            for (int np = 0; np < 4; ++np) {
                uint32_t v0, v1, v2, v3;
                ldsm_x4_t(v0, v1, v2, v3, aV + kcp * NPOFF + np * 32);
#pragma unroll
                for (int rf = 0; rf < 2; ++rf) {
                    mma16816(o[rf][2 * np], ah[rf], v0, v1);
                    mma16816(o[rf][2 * np + 1], ah[rf], v2, v3);
                }
            }
        }
    }

    // ---- write O ----
#pragma unroll
    for (int rf = 0; rf < 2; ++rf)
#pragma unroll
        for (int nt = 0; nt < 8; ++nt) {
            int col = nt * 8 + qq * 2;
            int r = row0 + rf * 16 + g;
            *reinterpret_cast<float2*>(Ob + (size_t)r * HD + col) =
                make_float2(o[rf][nt][0], o[rf][nt][1]);
            *reinterpret_cast<float2*>(Ob + (size_t)(r + 8) * HD + col) =
                make_float2(o[rf][nt][2], o[rf][nt][3]);
        }
}

extern "C" void kernel_launch(void* const* d_in, const int* in_sizes, int n_in,
                              void* d_out, int out_size) {
    const float* q = (const float*)d_in[0];
    const float* k = (const float*)d_in[1];
    const float* v = (const float*)d_in[2];
    (void)in_sizes; (void)n_in; (void)out_size;
    const int n4 = BHN * SEQ * HD / 4;
    convert_kernel<<<(2 * n4) / 256, 256>>>(k, v);
    dim3 grid(SEQ / BM, BHN);
    attn_kernel<<<grid, NTHREADS>>>(q, (float*)d_out);
}